// round 14
// baseline (speedup 1.0000x reference)
#include <cuda_runtime.h>
#include <cuda_bf16.h>

// UnifiedQuantumRegressor — all-tensor fused MLP + reduction.
//
// Algebra (verified since R1): all edge weights are 1.0 -> mean_w == 1.0
// exactly -> attn == q_out; the O(N^2) fidelity stage is dead.
// out = (sum_i tanh(relu(relu(s_i@W1+b1)@W2+b2)@Wq+bq)) @ Wh + bh
//
// Stages 1+2+3: mma.sync m16n8k16 bf16, 3-pass split-compensated
//   (Ahi*Bhi + Ahi*Blo + Alo*Bhi, fp32 accum) -> ~2^-17 effective precision.
// R14: padded weight arrays (unclamped prefetch), pointer-bump B addressing,
//   cross-stage B prefetch issued before each epilogue/__syncthreads so every
//   stage starts hot. Math and operand values bit-identical to R13.

#define NTHREADS 256
#define TM       32
#define NBLK     256          // 8192 / 32

// Packed B-fragments {bhi0,bhi1,blo0,blo1}; +2 ksteps padding for unclamped
// depth-2 prefetch (padding is read but never consumed by an MMA).
__device__ uint4        g_W1pack[34 * 32 * 32];     // 544 KB (32 real + 2 pad)
__device__ uint4        g_W2pack[18 * 32 * 32];     // 288 KB (16 real + 2 pad)
__device__ uint4        g_WQpack[18 * 8 * 32];      //  72 KB (16 real + 2 pad)
__device__ float        g_partials[NBLK];
__device__ unsigned int g_count;

static __device__ __forceinline__ unsigned pack_bf2(float a, float b) {
    __nv_bfloat162 h; h.x = __float2bfloat16(a); h.y = __float2bfloat16(b);
    return *(unsigned*)&h;
}
static __device__ __forceinline__ float bf_res(float x) {
    return x - __bfloat162float(__float2bfloat16(x));
}
static __device__ __forceinline__ void mma_bf16(float* d,
    unsigned a0, unsigned a1, unsigned a2, unsigned a3,
    unsigned b0, unsigned b1)
{
    asm volatile(
        "mma.sync.aligned.m16n8k16.row.col.f32.bf16.bf16.f32 "
        "{%0,%1,%2,%3}, {%4,%5,%6,%7}, {%8,%9}, {%0,%1,%2,%3};"
        : "+f"(d[0]), "+f"(d[1]), "+f"(d[2]), "+f"(d[3])
        : "r"(a0), "r"(a1), "r"(a2), "r"(a3), "r"(b0), "r"(b1));
}

// One s-step of 3-pass split MMAs for 2 m-tiles x 4 n8-blocks.
// A word layout: {hi_klo, hi_khi, lo_klo, lo_khi}.
static __device__ __forceinline__ void mma_group(
    float acc[2][4][4], const uint4* __restrict__ sbase, int a0,
    const uint4 B[4])
{
    #pragma unroll
    for (int mt = 0; mt < 2; ++mt) {
        const uint4 A0 = sbase[mt * 64 + a0];        // row g
        const uint4 A1 = sbase[mt * 64 + a0 + 32];   // row g+8
        #pragma unroll
        for (int nbi = 0; nbi < 4; ++nbi) {
            mma_bf16(acc[mt][nbi], A0.x, A1.x, A0.y, A1.y, B[nbi].x, B[nbi].y); // hi*hi
            mma_bf16(acc[mt][nbi], A0.x, A1.x, A0.y, A1.y, B[nbi].z, B[nbi].w); // hi*lo
            mma_bf16(acc[mt][nbi], A0.z, A1.z, A0.w, A1.w, B[nbi].x, B[nbi].y); // lo*hi
        }
    }
}

// ---- prep: split W1/W2/Wq into bf16 hi/lo, pack in B-fragment order ----
__global__ __launch_bounds__(512) void prep_W_kernel(
    const float* __restrict__ W1, const float* __restrict__ W2,
    const float* __restrict__ Wq)
{
    int idx = blockIdx.x * blockDim.x + threadIdx.x;     // 0 .. 53247
    const float* W;
    uint4* dst;
    int li, nb, s, ncols;
    if (idx < 32 * 32 * 32) {
        W = W1; dst = g_W1pack; li = idx;
        nb = (li >> 5) & 31; s = li >> 10; ncols = 256;
    } else if (idx < 48 * 32 * 32) {
        W = W2; dst = g_W2pack; li = idx - 32 * 32 * 32;
        nb = (li >> 5) & 31; s = li >> 10; ncols = 256;
    } else if (idx < 48 * 32 * 32 + 16 * 8 * 32) {
        W = Wq; dst = g_WQpack; li = idx - 48 * 32 * 32;
        nb = (li >> 5) & 7;  s = li >> 8;  ncols = 64;
    } else return;
    const int l = li & 31;
    const int g = l >> 2, t = l & 3;
    const int n  = nb * 8 + g;
    const int k0 = s * 16 + 2 * t;
    const float w00 = W[(k0    ) * ncols + n];
    const float w01 = W[(k0 + 1) * ncols + n];
    const float w10 = W[(k0 + 8) * ncols + n];
    const float w11 = W[(k0 + 9) * ncols + n];
    uint4 v;
    v.x = pack_bf2(w00, w01);
    v.y = pack_bf2(w10, w11);
    v.z = pack_bf2(bf_res(w00), bf_res(w01));
    v.w = pack_bf2(bf_res(w10), bf_res(w11));
    dst[li] = v;
}

__global__ __launch_bounds__(NTHREADS, 2) void fused_mlp_kernel(
    const float* __restrict__ S,   // [8192,512]
    const float* __restrict__ b1,  // [256]
    const float* __restrict__ b2,  // [256]
    const float* __restrict__ bq,  // [64]
    const float* __restrict__ Wh,  // [64]
    const float* __restrict__ bh,  // [1]
    float* __restrict__ out)
{
    extern __shared__ uint4 sm4[];     // 4096 uint4 = 64 KB
    uint4* sA1 = sm4;                  // [32 s][32 r][4 t]  S tile
    uint4* sA2 = sm4;                  // [16 s][32 r][4 t]  enc1 (overlays)
    uint4* sA3 = sm4 + 2048;           // [16 s][32 r][4 t]  enc2
    __shared__ float sRed[8];
    __shared__ int   sIsLast;

    const int tid  = threadIdx.x;
    const int wq   = tid >> 5;          // warp 0..7
    const int lane = tid & 31;
    const int g = lane >> 2, t = lane & 3;
    const int a0 = g * 4 + t;
    const int row0 = blockIdx.x * TM;

    // B prefetch buffers, shared across stages (dead between mainloops).
    uint4 B0[4], B1[4];

    // ---- issue stage-1 B(0),B(1) prefetch first: covered by S DRAM loads ----
    const uint4* bb1 = g_W1pack + wq * 4 * 32 + lane;
    #pragma unroll
    for (int nbi = 0; nbi < 4; ++nbi) B0[nbi] = bb1[nbi * 32];
    #pragma unroll
    for (int nbi = 0; nbi < 4; ++nbi) B1[nbi] = bb1[1024 + nbi * 32];

    // ---- stage S tile [32 x 512] into smem: interleaved hi/lo frag words ----
    {
        const int r  = tid >> 3;            // 0..31
        const int s0 = (tid & 7) * 4;       // 4 ksteps per thread
        const float* Srow = S + (size_t)(row0 + r) * 512;
        #pragma unroll
        for (int i = 0; i < 4; ++i) {
            const int s = s0 + i;
            const float4 x0 = *(const float4*)(Srow + s * 16);
            const float4 x1 = *(const float4*)(Srow + s * 16 + 4);
            const float4 x2 = *(const float4*)(Srow + s * 16 + 8);
            const float4 x3 = *(const float4*)(Srow + s * 16 + 12);
            const int base = s * 128 + r * 4;
            sA1[base + 0] = make_uint4(pack_bf2(x0.x, x0.y), pack_bf2(x2.x, x2.y),
                                       pack_bf2(bf_res(x0.x), bf_res(x0.y)),
                                       pack_bf2(bf_res(x2.x), bf_res(x2.y)));
            sA1[base + 1] = make_uint4(pack_bf2(x0.z, x0.w), pack_bf2(x2.z, x2.w),
                                       pack_bf2(bf_res(x0.z), bf_res(x0.w)),
                                       pack_bf2(bf_res(x2.z), bf_res(x2.w)));
            sA1[base + 2] = make_uint4(pack_bf2(x1.x, x1.y), pack_bf2(x3.x, x3.y),
                                       pack_bf2(bf_res(x1.x), bf_res(x1.y)),
                                       pack_bf2(bf_res(x3.x), bf_res(x3.y)));
            sA1[base + 3] = make_uint4(pack_bf2(x1.z, x1.w), pack_bf2(x3.z, x3.w),
                                       pack_bf2(bf_res(x1.z), bf_res(x1.w)),
                                       pack_bf2(bf_res(x3.z), bf_res(x3.w)));
        }
    }
    __syncthreads();

    // ============ stage 1: enc1 = relu(S @ W1 + b1) ============
    float acc1[2][4][4];
    {
        #pragma unroll
        for (int mt = 0; mt < 2; ++mt)
            #pragma unroll
            for (int nbi = 0; nbi < 4; ++nbi)
                #pragma unroll
                for (int j = 0; j < 4; ++j) acc1[mt][nbi][j] = 0.f;

        const uint4* bp = bb1;              // bumped by 2048 per outer iter
        const uint4* sa = sA1;
        #pragma unroll 1
        for (int s = 0; s < 32; s += 2, bp += 2048, sa += 256) {
            {   // sub-iter s: consume B0, prefetch s+2 (pad-safe)
                uint4 Bp[4];
                #pragma unroll
                for (int nbi = 0; nbi < 4; ++nbi) Bp[nbi] = bp[2048 + nbi * 32];
                mma_group(acc1, sa, a0, B0);
                #pragma unroll
                for (int nbi = 0; nbi < 4; ++nbi) B0[nbi] = Bp[nbi];
            }
            {   // sub-iter s+1: consume B1, prefetch s+3 (pad-safe)
                uint4 Bp[4];
                #pragma unroll
                for (int nbi = 0; nbi < 4; ++nbi) Bp[nbi] = bp[3072 + nbi * 32];
                mma_group(acc1, sa + 128, a0, B1);
                #pragma unroll
                for (int nbi = 0; nbi < 4; ++nbi) B1[nbi] = Bp[nbi];
            }
        }
    }

    // prefetch stage-2 B(0),B(1) NOW — lands during epilogue + barrier
    const uint4* bb2 = g_W2pack + wq * 4 * 32 + lane;
    #pragma unroll
    for (int nbi = 0; nbi < 4; ++nbi) B0[nbi] = bb2[nbi * 32];
    #pragma unroll
    for (int nbi = 0; nbi < 4; ++nbi) B1[nbi] = bb2[1024 + nbi * 32];

    __syncthreads();                       // sA1 reads done; region reusable

    // epilogue 1: bias+relu -> enc1 as interleaved hi/lo A-words (sA2)
    {
        #pragma unroll
        for (int nbi = 0; nbi < 4; ++nbi) {
            const int n0 = wq * 32 + nbi * 8 + 2 * t;
            const float bb0 = b1[n0], bbv = b1[n0 + 1];
            const int s2 = 2 * wq + (nbi >> 1);
            const int half = nbi & 1;
            #pragma unroll
            for (int mt = 0; mt < 2; ++mt) {
                const int mlo = mt * 16 + g;
                const float vl0 = fmaxf(acc1[mt][nbi][0] + bb0, 0.f);
                const float vl1 = fmaxf(acc1[mt][nbi][1] + bbv, 0.f);
                const float vh0 = fmaxf(acc1[mt][nbi][2] + bb0, 0.f);
                const float vh1 = fmaxf(acc1[mt][nbi][3] + bbv, 0.f);
                unsigned* plo = (unsigned*)&sA2[s2 * 128 + mlo * 4 + t];
                unsigned* phi = plo + 32 * 4;                  // row +8
                plo[half]     = pack_bf2(vl0, vl1);
                plo[2 + half] = pack_bf2(bf_res(vl0), bf_res(vl1));
                phi[half]     = pack_bf2(vh0, vh1);
                phi[2 + half] = pack_bf2(bf_res(vh0), bf_res(vh1));
            }
        }
    }
    __syncthreads();

    // ============ stage 2: enc2 = relu(enc1 @ W2 + b2) ============
    float acc2[2][4][4];
    {
        #pragma unroll
        for (int mt = 0; mt < 2; ++mt)
            #pragma unroll
            for (int nbi = 0; nbi < 4; ++nbi)
                #pragma unroll
                for (int j = 0; j < 4; ++j) acc2[mt][nbi][j] = 0.f;

        const uint4* bp = bb2;
        const uint4* sa = sA2;
        #pragma unroll 1
        for (int s = 0; s < 16; s += 2, bp += 2048, sa += 256) {
            {
                uint4 Bp[4];
                #pragma unroll
                for (int nbi = 0; nbi < 4; ++nbi) Bp[nbi] = bp[2048 + nbi * 32];
                mma_group(acc2, sa, a0, B0);
                #pragma unroll
                for (int nbi = 0; nbi < 4; ++nbi) B0[nbi] = Bp[nbi];
            }
            {
                uint4 Bp[4];
                #pragma unroll
                for (int nbi = 0; nbi < 4; ++nbi) Bp[nbi] = bp[3072 + nbi * 32];
                mma_group(acc2, sa + 128, a0, B1);
                #pragma unroll
                for (int nbi = 0; nbi < 4; ++nbi) B1[nbi] = Bp[nbi];
            }
        }
    }

    // prefetch stage-3 C(0),C(1) NOW — lands during epilogue + barrier
    const uint4* qb = g_WQpack + wq * 32 + lane;    // + s*256
    uint4 C0 = qb[0];
    uint4 C1 = qb[256];

    // epilogue 2: bias+relu -> enc2 A-words into sA3 (distinct region; no
    // readers until the next __syncthreads, writes are thread-private data).
    {
        #pragma unroll
        for (int nbi = 0; nbi < 4; ++nbi) {
            const int n0 = wq * 32 + nbi * 8 + 2 * t;
            const float bb0 = b2[n0], bbv = b2[n0 + 1];
            const int s2 = 2 * wq + (nbi >> 1);
            const int half = nbi & 1;
            #pragma unroll
            for (int mt = 0; mt < 2; ++mt) {
                const int mlo = mt * 16 + g;
                const float vl0 = fmaxf(acc2[mt][nbi][0] + bb0, 0.f);
                const float vl1 = fmaxf(acc2[mt][nbi][1] + bbv, 0.f);
                const float vh0 = fmaxf(acc2[mt][nbi][2] + bb0, 0.f);
                const float vh1 = fmaxf(acc2[mt][nbi][3] + bbv, 0.f);
                unsigned* plo = (unsigned*)&sA3[s2 * 128 + mlo * 4 + t];
                unsigned* phi = plo + 32 * 4;
                plo[half]     = pack_bf2(vl0, vl1);
                plo[2 + half] = pack_bf2(bf_res(vl0), bf_res(vl1));
                phi[half]     = pack_bf2(vh0, vh1);
                phi[2 + half] = pack_bf2(bf_res(vh0), bf_res(vh1));
            }
        }
    }
    __syncthreads();

    // ====== stage 3: qpre = enc2 @ Wq — warp wq owns n8-block wq ======
    float acc3[2][4];
    {
        #pragma unroll
        for (int mt = 0; mt < 2; ++mt)
            #pragma unroll
            for (int j = 0; j < 4; ++j) acc3[mt][j] = 0.f;

        const uint4* qp = qb;               // bumped by 512 per outer iter
        const uint4* sa = sA3;
        #pragma unroll 1
        for (int s = 0; s < 16; s += 2, qp += 512, sa += 256) {
            {
                const uint4 Cp = qp[512];           // s+2, pad-safe
                #pragma unroll
                for (int mt = 0; mt < 2; ++mt) {
                    const uint4 A0 = sa[mt * 64 + a0];
                    const uint4 A1 = sa[mt * 64 + a0 + 32];
                    mma_bf16(acc3[mt], A0.x, A1.x, A0.y, A1.y, C0.x, C0.y);
                    mma_bf16(acc3[mt], A0.x, A1.x, A0.y, A1.y, C0.z, C0.w);
                    mma_bf16(acc3[mt], A0.z, A1.z, A0.w, A1.w, C0.x, C0.y);
                }
                C0 = Cp;
            }
            {
                const uint4 Cp = qp[768];           // s+3, pad-safe
                #pragma unroll
                for (int mt = 0; mt < 2; ++mt) {
                    const uint4 A0 = sa[128 + mt * 64 + a0];
                    const uint4 A1 = sa[128 + mt * 64 + a0 + 32];
                    mma_bf16(acc3[mt], A0.x, A1.x, A0.y, A1.y, C1.x, C1.y);
                    mma_bf16(acc3[mt], A0.x, A1.x, A0.y, A1.y, C1.z, C1.w);
                    mma_bf16(acc3[mt], A0.z, A1.z, A0.w, A1.w, C1.x, C1.y);
                }
                C1 = Cp;
            }
        }
    }

    // epilogue 3: q = tanh(qpre + bq); part = q . Wh
    float part;
    {
        const int n0 = wq * 8 + 2 * t;
        const float bq0 = bq[n0], bq1 = bq[n0 + 1];
        const float wh0 = Wh[n0], wh1 = Wh[n0 + 1];
        part = 0.f;
        #pragma unroll
        for (int mt = 0; mt < 2; ++mt) {
            part += tanhf(acc3[mt][0] + bq0) * wh0
                  + tanhf(acc3[mt][1] + bq1) * wh1
                  + tanhf(acc3[mt][2] + bq0) * wh0
                  + tanhf(acc3[mt][3] + bq1) * wh1;
        }
    }

    // ---- block reduce (fixed order) ----
    #pragma unroll
    for (int o = 16; o > 0; o >>= 1)
        part += __shfl_down_sync(0xffffffffu, part, o);
    if (lane == 0) sRed[wq] = part;
    __syncthreads();

    if (tid == 0) {
        float tot = 0.f;
        #pragma unroll
        for (int i = 0; i < 8; ++i) tot += sRed[i];
        g_partials[blockIdx.x] = tot;
        __threadfence();
        unsigned int c = atomicAdd(&g_count, 1u);
        sIsLast = (c == NBLK - 1u);
    }
    __syncthreads();

    // ---- last-done block: deterministic final reduction ----
    if (sIsLast) {
        volatile float* gp = g_partials;
        float v = gp[tid];                       // 256 partials, fixed order
        #pragma unroll
        for (int o = 16; o > 0; o >>= 1)
            v += __shfl_down_sync(0xffffffffu, v, o);
        if (lane == 0) sRed[wq] = v;
        __syncthreads();
        if (tid == 0) {
            float tfin = 0.f;
            #pragma unroll
            for (int i = 0; i < 8; ++i) tfin += sRed[i];
            out[0] = tfin + bh[0];
            g_count = 0;                           // self-reset for graph replay
        }
    }
}

extern "C" void kernel_launch(void* const* d_in, const int* in_sizes, int n_in,
                              void* d_out, int out_size)
{
    const float* S  = (const float*)d_in[0];
    const float* W1 = (const float*)d_in[1];
    const float* b1 = (const float*)d_in[2];
    const float* W2 = (const float*)d_in[3];
    const float* b2 = (const float*)d_in[4];
    const float* Wq = (const float*)d_in[5];
    const float* bq = (const float*)d_in[6];
    const float* Wh = (const float*)d_in[7];
    const float* bh = (const float*)d_in[8];
    float* out = (float*)d_out;

    const int dynsm = 65536;
    cudaFuncSetAttribute(fused_mlp_kernel,
                         cudaFuncAttributeMaxDynamicSharedMemorySize, dynsm);

    prep_W_kernel<<<104, 512>>>(W1, W2, Wq);
    fused_mlp_kernel<<<NBLK, NTHREADS, dynsm>>>(S, b1, b2, bq, Wh, bh, out);
}

// round 15
// speedup vs baseline: 1.0200x; 1.0200x over previous
#include <cuda_runtime.h>
#include <cuda_bf16.h>

// UnifiedQuantumRegressor — all-tensor fused MLP + reduction, dual-tile CTAs.
//
// Algebra (verified since R1): all edge weights are 1.0 -> mean_w == 1.0
// exactly -> attn == q_out; the O(N^2) fidelity stage is dead.
// out = (sum_i tanh(relu(relu(s_i@W1+b1)@W2+b2)@Wq+bq)) @ Wh + bh
//
// Stages 1+2+3: mma.sync m16n8k16 bf16, 3-pass split-compensated
//   (Ahi*Bhi + Ahi*Blo + Alo*Bhi, fp32 accum) -> ~2^-17 effective precision.
// R15: TM=64 as TWO independent 32-row tiles per CTA sharing B-fragment
//   registers: B loaded once serves both tiles -> 1.0 L1-wavefront/MMA
//   (was 1.33), 2x accumulator ILP, half the B L2 traffic. grid=128, 1 CTA/SM.

#define NTHREADS 256
#define TM       64
#define NBLK     128          // 8192 / 64

// Packed B-fragments {bhi0,bhi1,blo0,blo1}; +2 ksteps padding for unclamped
// depth-2 prefetch (padding is read but never consumed by an MMA).
__device__ uint4        g_W1pack[34 * 32 * 32];     // 544 KB (32 real + 2 pad)
__device__ uint4        g_W2pack[18 * 32 * 32];     // 288 KB (16 real + 2 pad)
__device__ uint4        g_WQpack[18 * 8 * 32];      //  72 KB (16 real + 2 pad)
__device__ float        g_partials[NBLK];
__device__ unsigned int g_count;

static __device__ __forceinline__ unsigned pack_bf2(float a, float b) {
    __nv_bfloat162 h; h.x = __float2bfloat16(a); h.y = __float2bfloat16(b);
    return *(unsigned*)&h;
}
static __device__ __forceinline__ float bf_res(float x) {
    return x - __bfloat162float(__float2bfloat16(x));
}
static __device__ __forceinline__ void mma_bf16(float* d,
    unsigned a0, unsigned a1, unsigned a2, unsigned a3,
    unsigned b0, unsigned b1)
{
    asm volatile(
        "mma.sync.aligned.m16n8k16.row.col.f32.bf16.bf16.f32 "
        "{%0,%1,%2,%3}, {%4,%5,%6,%7}, {%8,%9}, {%0,%1,%2,%3};"
        : "+f"(d[0]), "+f"(d[1]), "+f"(d[2]), "+f"(d[3])
        : "r"(a0), "r"(a1), "r"(a2), "r"(a3), "r"(b0), "r"(b1));
}

// One s-step of 3-pass split MMAs for 2 m-tiles x 4 n8-blocks.
// A word layout: {hi_klo, hi_khi, lo_klo, lo_khi}.
static __device__ __forceinline__ void mma_group(
    float acc[2][4][4], const uint4* __restrict__ sbase, int a0,
    const uint4 B[4])
{
    #pragma unroll
    for (int mt = 0; mt < 2; ++mt) {
        const uint4 A0 = sbase[mt * 64 + a0];        // row g
        const uint4 A1 = sbase[mt * 64 + a0 + 32];   // row g+8
        #pragma unroll
        for (int nbi = 0; nbi < 4; ++nbi) {
            mma_bf16(acc[mt][nbi], A0.x, A1.x, A0.y, A1.y, B[nbi].x, B[nbi].y); // hi*hi
            mma_bf16(acc[mt][nbi], A0.x, A1.x, A0.y, A1.y, B[nbi].z, B[nbi].w); // hi*lo
            mma_bf16(acc[mt][nbi], A0.z, A1.z, A0.w, A1.w, B[nbi].x, B[nbi].y); // lo*hi
        }
    }
}

// ---- prep: split W1/W2/Wq into bf16 hi/lo, pack in B-fragment order ----
__global__ __launch_bounds__(512) void prep_W_kernel(
    const float* __restrict__ W1, const float* __restrict__ W2,
    const float* __restrict__ Wq)
{
    int idx = blockIdx.x * blockDim.x + threadIdx.x;     // 0 .. 53247
    const float* W;
    uint4* dst;
    int li, nb, s, ncols;
    if (idx < 32 * 32 * 32) {
        W = W1; dst = g_W1pack; li = idx;
        nb = (li >> 5) & 31; s = li >> 10; ncols = 256;
    } else if (idx < 48 * 32 * 32) {
        W = W2; dst = g_W2pack; li = idx - 32 * 32 * 32;
        nb = (li >> 5) & 31; s = li >> 10; ncols = 256;
    } else if (idx < 48 * 32 * 32 + 16 * 8 * 32) {
        W = Wq; dst = g_WQpack; li = idx - 48 * 32 * 32;
        nb = (li >> 5) & 7;  s = li >> 8;  ncols = 64;
    } else return;
    const int l = li & 31;
    const int g = l >> 2, t = l & 3;
    const int n  = nb * 8 + g;
    const int k0 = s * 16 + 2 * t;
    const float w00 = W[(k0    ) * ncols + n];
    const float w01 = W[(k0 + 1) * ncols + n];
    const float w10 = W[(k0 + 8) * ncols + n];
    const float w11 = W[(k0 + 9) * ncols + n];
    uint4 v;
    v.x = pack_bf2(w00, w01);
    v.y = pack_bf2(w10, w11);
    v.z = pack_bf2(bf_res(w00), bf_res(w01));
    v.w = pack_bf2(bf_res(w10), bf_res(w11));
    dst[li] = v;
}

__global__ __launch_bounds__(NTHREADS, 1) void fused_mlp_kernel(
    const float* __restrict__ S,   // [8192,512]
    const float* __restrict__ b1,  // [256]
    const float* __restrict__ b2,  // [256]
    const float* __restrict__ bq,  // [64]
    const float* __restrict__ Wh,  // [64]
    const float* __restrict__ bh,  // [1]
    float* __restrict__ out)
{
    extern __shared__ uint4 sm4[];     // 8192 uint4 = 128 KB
    // Per tile u (0/1), base tb = u*4096:
    //   sA1: [tb, tb+4096)  [32 s][32 r][4 t]  S tile
    //   sA2: [tb, tb+2048)  enc1 (overlays sA1 after stage 1)
    //   sA3: [tb+2048, tb+4096)  enc2
    __shared__ float sRed[8];
    __shared__ int   sIsLast;

    const int tid  = threadIdx.x;
    const int wq   = tid >> 5;          // warp 0..7
    const int lane = tid & 31;
    const int g = lane >> 2, t = lane & 3;
    const int a0 = g * 4 + t;
    const int row0 = blockIdx.x * TM;

    // B prefetch buffers, shared across stages (dead between mainloops).
    uint4 B0[4], B1[4];

    // ---- issue stage-1 B(0),B(1) prefetch first: covered by S DRAM loads ----
    const uint4* bb1 = g_W1pack + wq * 4 * 32 + lane;
    #pragma unroll
    for (int nbi = 0; nbi < 4; ++nbi) B0[nbi] = bb1[nbi * 32];
    #pragma unroll
    for (int nbi = 0; nbi < 4; ++nbi) B1[nbi] = bb1[1024 + nbi * 32];

    // ---- stage S [64 x 512] into smem: interleaved hi/lo frag words, 2 tiles ----
    #pragma unroll
    for (int u = 0; u < 2; ++u) {
        uint4* sA1 = sm4 + u * 4096;
        const int r  = tid >> 3;            // 0..31
        const int s0 = (tid & 7) * 4;       // 4 ksteps per thread
        const float* Srow = S + (size_t)(row0 + u * 32 + r) * 512;
        #pragma unroll
        for (int i = 0; i < 4; ++i) {
            const int s = s0 + i;
            const float4 x0 = *(const float4*)(Srow + s * 16);
            const float4 x1 = *(const float4*)(Srow + s * 16 + 4);
            const float4 x2 = *(const float4*)(Srow + s * 16 + 8);
            const float4 x3 = *(const float4*)(Srow + s * 16 + 12);
            const int base = s * 128 + r * 4;
            sA1[base + 0] = make_uint4(pack_bf2(x0.x, x0.y), pack_bf2(x2.x, x2.y),
                                       pack_bf2(bf_res(x0.x), bf_res(x0.y)),
                                       pack_bf2(bf_res(x2.x), bf_res(x2.y)));
            sA1[base + 1] = make_uint4(pack_bf2(x0.z, x0.w), pack_bf2(x2.z, x2.w),
                                       pack_bf2(bf_res(x0.z), bf_res(x0.w)),
                                       pack_bf2(bf_res(x2.z), bf_res(x2.w)));
            sA1[base + 2] = make_uint4(pack_bf2(x1.x, x1.y), pack_bf2(x3.x, x3.y),
                                       pack_bf2(bf_res(x1.x), bf_res(x1.y)),
                                       pack_bf2(bf_res(x3.x), bf_res(x3.y)));
            sA1[base + 3] = make_uint4(pack_bf2(x1.z, x1.w), pack_bf2(x3.z, x3.w),
                                       pack_bf2(bf_res(x1.z), bf_res(x1.w)),
                                       pack_bf2(bf_res(x3.z), bf_res(x3.w)));
        }
    }
    __syncthreads();

    // ============ stage 1: enc1 = relu(S @ W1 + b1) — dual tile ============
    float acc1[2][2][4][4];               // [tile][mt][nbi][frag]
    {
        #pragma unroll
        for (int u = 0; u < 2; ++u)
            #pragma unroll
            for (int mt = 0; mt < 2; ++mt)
                #pragma unroll
                for (int nbi = 0; nbi < 4; ++nbi)
                    #pragma unroll
                    for (int j = 0; j < 4; ++j) acc1[u][mt][nbi][j] = 0.f;

        const uint4* bp = bb1;              // bumped by 2048 per outer iter
        const uint4* sa = sm4;
        #pragma unroll 1
        for (int s = 0; s < 32; s += 2, bp += 2048, sa += 256) {
            {   // sub-iter s: consume B0 on BOTH tiles, prefetch s+2
                uint4 Bp[4];
                #pragma unroll
                for (int nbi = 0; nbi < 4; ++nbi) Bp[nbi] = bp[2048 + nbi * 32];
                mma_group(acc1[0], sa,        a0, B0);
                mma_group(acc1[1], sa + 4096, a0, B0);
                #pragma unroll
                for (int nbi = 0; nbi < 4; ++nbi) B0[nbi] = Bp[nbi];
            }
            {   // sub-iter s+1: consume B1 on BOTH tiles, prefetch s+3
                uint4 Bp[4];
                #pragma unroll
                for (int nbi = 0; nbi < 4; ++nbi) Bp[nbi] = bp[3072 + nbi * 32];
                mma_group(acc1[0], sa + 128,        a0, B1);
                mma_group(acc1[1], sa + 128 + 4096, a0, B1);
                #pragma unroll
                for (int nbi = 0; nbi < 4; ++nbi) B1[nbi] = Bp[nbi];
            }
        }
    }

    // prefetch stage-2 B(0),B(1) NOW — lands during epilogue + barrier
    const uint4* bb2 = g_W2pack + wq * 4 * 32 + lane;
    #pragma unroll
    for (int nbi = 0; nbi < 4; ++nbi) B0[nbi] = bb2[nbi * 32];
    #pragma unroll
    for (int nbi = 0; nbi < 4; ++nbi) B1[nbi] = bb2[1024 + nbi * 32];

    __syncthreads();                       // sA1 reads done; regions reusable

    // epilogue 1: bias+relu -> enc1 as interleaved hi/lo A-words (sA2 per tile)
    {
        #pragma unroll
        for (int u = 0; u < 2; ++u) {
            uint4* sA2 = sm4 + u * 4096;
            #pragma unroll
            for (int nbi = 0; nbi < 4; ++nbi) {
                const int n0 = wq * 32 + nbi * 8 + 2 * t;
                const float bb0 = b1[n0], bbv = b1[n0 + 1];
                const int s2 = 2 * wq + (nbi >> 1);
                const int half = nbi & 1;
                #pragma unroll
                for (int mt = 0; mt < 2; ++mt) {
                    const int mlo = mt * 16 + g;
                    const float vl0 = fmaxf(acc1[u][mt][nbi][0] + bb0, 0.f);
                    const float vl1 = fmaxf(acc1[u][mt][nbi][1] + bbv, 0.f);
                    const float vh0 = fmaxf(acc1[u][mt][nbi][2] + bb0, 0.f);
                    const float vh1 = fmaxf(acc1[u][mt][nbi][3] + bbv, 0.f);
                    unsigned* plo = (unsigned*)&sA2[s2 * 128 + mlo * 4 + t];
                    unsigned* phi = plo + 32 * 4;                  // row +8
                    plo[half]     = pack_bf2(vl0, vl1);
                    plo[2 + half] = pack_bf2(bf_res(vl0), bf_res(vl1));
                    phi[half]     = pack_bf2(vh0, vh1);
                    phi[2 + half] = pack_bf2(bf_res(vh0), bf_res(vh1));
                }
            }
        }
    }
    __syncthreads();

    // ============ stage 2: enc2 = relu(enc1 @ W2 + b2) — dual tile ============
    float acc2[2][2][4][4];
    {
        #pragma unroll
        for (int u = 0; u < 2; ++u)
            #pragma unroll
            for (int mt = 0; mt < 2; ++mt)
                #pragma unroll
                for (int nbi = 0; nbi < 4; ++nbi)
                    #pragma unroll
                    for (int j = 0; j < 4; ++j) acc2[u][mt][nbi][j] = 0.f;

        const uint4* bp = bb2;
        const uint4* sa = sm4;
        #pragma unroll 1
        for (int s = 0; s < 16; s += 2, bp += 2048, sa += 256) {
            {
                uint4 Bp[4];
                #pragma unroll
                for (int nbi = 0; nbi < 4; ++nbi) Bp[nbi] = bp[2048 + nbi * 32];
                mma_group(acc2[0], sa,        a0, B0);
                mma_group(acc2[1], sa + 4096, a0, B0);
                #pragma unroll
                for (int nbi = 0; nbi < 4; ++nbi) B0[nbi] = Bp[nbi];
            }
            {
                uint4 Bp[4];
                #pragma unroll
                for (int nbi = 0; nbi < 4; ++nbi) Bp[nbi] = bp[3072 + nbi * 32];
                mma_group(acc2[0], sa + 128,        a0, B1);
                mma_group(acc2[1], sa + 128 + 4096, a0, B1);
                #pragma unroll
                for (int nbi = 0; nbi < 4; ++nbi) B1[nbi] = Bp[nbi];
            }
        }
    }

    // prefetch stage-3 C(0),C(1) NOW — lands during epilogue + barrier
    const uint4* qb = g_WQpack + wq * 32 + lane;    // + s*256
    uint4 C0 = qb[0];
    uint4 C1 = qb[256];

    // epilogue 2: bias+relu -> enc2 A-words into sA3 (tb+2048; no readers
    // until next __syncthreads, writes are thread-private data).
    {
        #pragma unroll
        for (int u = 0; u < 2; ++u) {
            uint4* sA3 = sm4 + u * 4096 + 2048;
            #pragma unroll
            for (int nbi = 0; nbi < 4; ++nbi) {
                const int n0 = wq * 32 + nbi * 8 + 2 * t;
                const float bb0 = b2[n0], bbv = b2[n0 + 1];
                const int s2 = 2 * wq + (nbi >> 1);
                const int half = nbi & 1;
                #pragma unroll
                for (int mt = 0; mt < 2; ++mt) {
                    const int mlo = mt * 16 + g;
                    const float vl0 = fmaxf(acc2[u][mt][nbi][0] + bb0, 0.f);
                    const float vl1 = fmaxf(acc2[u][mt][nbi][1] + bbv, 0.f);
                    const float vh0 = fmaxf(acc2[u][mt][nbi][2] + bb0, 0.f);
                    const float vh1 = fmaxf(acc2[u][mt][nbi][3] + bbv, 0.f);
                    unsigned* plo = (unsigned*)&sA3[s2 * 128 + mlo * 4 + t];
                    unsigned* phi = plo + 32 * 4;
                    plo[half]     = pack_bf2(vl0, vl1);
                    plo[2 + half] = pack_bf2(bf_res(vl0), bf_res(vl1));
                    phi[half]     = pack_bf2(vh0, vh1);
                    phi[2 + half] = pack_bf2(bf_res(vh0), bf_res(vh1));
                }
            }
        }
    }
    __syncthreads();

    // ====== stage 3: qpre = enc2 @ Wq — dual tile; warp wq owns n8-block wq ======
    float acc3[2][2][4];                   // [tile][mt][frag]
    {
        #pragma unroll
        for (int u = 0; u < 2; ++u)
            #pragma unroll
            for (int mt = 0; mt < 2; ++mt)
                #pragma unroll
                for (int j = 0; j < 4; ++j) acc3[u][mt][j] = 0.f;

        const uint4* qp = qb;               // bumped by 512 per outer iter
        const uint4* sa = sm4 + 2048;       // sA3 tile 0
        #pragma unroll 1
        for (int s = 0; s < 16; s += 2, qp += 512, sa += 256) {
            {
                const uint4 Cp = qp[512];           // s+2, pad-safe
                #pragma unroll
                for (int u = 0; u < 2; ++u)
                    #pragma unroll
                    for (int mt = 0; mt < 2; ++mt) {
                        const uint4 A0 = sa[u * 4096 + mt * 64 + a0];
                        const uint4 A1 = sa[u * 4096 + mt * 64 + a0 + 32];
                        mma_bf16(acc3[u][mt], A0.x, A1.x, A0.y, A1.y, C0.x, C0.y);
                        mma_bf16(acc3[u][mt], A0.x, A1.x, A0.y, A1.y, C0.z, C0.w);
                        mma_bf16(acc3[u][mt], A0.z, A1.z, A0.w, A1.w, C0.x, C0.y);
                    }
                C0 = Cp;
            }
            {
                const uint4 Cp = qp[768];           // s+3, pad-safe
                #pragma unroll
                for (int u = 0; u < 2; ++u)
                    #pragma unroll
                    for (int mt = 0; mt < 2; ++mt) {
                        const uint4 A0 = sa[u * 4096 + 128 + mt * 64 + a0];
                        const uint4 A1 = sa[u * 4096 + 128 + mt * 64 + a0 + 32];
                        mma_bf16(acc3[u][mt], A0.x, A1.x, A0.y, A1.y, C1.x, C1.y);
                        mma_bf16(acc3[u][mt], A0.x, A1.x, A0.y, A1.y, C1.z, C1.w);
                        mma_bf16(acc3[u][mt], A0.z, A1.z, A0.w, A1.w, C1.x, C1.y);
                    }
                C1 = Cp;
            }
        }
    }

    // epilogue 3: q = tanh(qpre + bq); part = q . Wh  (both tiles)
    float part;
    {
        const int n0 = wq * 8 + 2 * t;
        const float bq0 = bq[n0], bq1 = bq[n0 + 1];
        const float wh0 = Wh[n0], wh1 = Wh[n0 + 1];
        part = 0.f;
        #pragma unroll
        for (int u = 0; u < 2; ++u)
            #pragma unroll
            for (int mt = 0; mt < 2; ++mt) {
                part += tanhf(acc3[u][mt][0] + bq0) * wh0
                      + tanhf(acc3[u][mt][1] + bq1) * wh1
                      + tanhf(acc3[u][mt][2] + bq0) * wh0
                      + tanhf(acc3[u][mt][3] + bq1) * wh1;
            }
    }

    // ---- block reduce (fixed order) ----
    #pragma unroll
    for (int o = 16; o > 0; o >>= 1)
        part += __shfl_down_sync(0xffffffffu, part, o);
    if (lane == 0) sRed[wq] = part;
    __syncthreads();

    if (tid == 0) {
        float tot = 0.f;
        #pragma unroll
        for (int i = 0; i < 8; ++i) tot += sRed[i];
        g_partials[blockIdx.x] = tot;
        __threadfence();
        unsigned int c = atomicAdd(&g_count, 1u);
        sIsLast = (c == NBLK - 1u);
    }
    __syncthreads();

    // ---- last-done block: deterministic final reduction (128 partials) ----
    if (sIsLast) {
        volatile float* gp = g_partials;
        float v = (tid < NBLK) ? gp[tid] : 0.f;
        #pragma unroll
        for (int o = 16; o > 0; o >>= 1)
            v += __shfl_down_sync(0xffffffffu, v, o);
        if (lane == 0) sRed[wq] = v;
        __syncthreads();
        if (tid == 0) {
            float tfin = 0.f;
            #pragma unroll
            for (int i = 0; i < 8; ++i) tfin += sRed[i];
            out[0] = tfin + bh[0];
            g_count = 0;                           // self-reset for graph replay
        }
    }
}

extern "C" void kernel_launch(void* const* d_in, const int* in_sizes, int n_in,
                              void* d_out, int out_size)
{
    const float* S  = (const float*)d_in[0];
    const float* W1 = (const float*)d_in[1];
    const float* b1 = (const float*)d_in[2];
    const float* W2 = (const float*)d_in[3];
    const float* b2 = (const float*)d_in[4];
    const float* Wq = (const float*)d_in[5];
    const float* bq = (const float*)d_in[6];
    const float* Wh = (const float*)d_in[7];
    const float* bh = (const float*)d_in[8];
    float* out = (float*)d_out;

    const int dynsm = 131072;    // two 64KB tile regions
    cudaFuncSetAttribute(fused_mlp_kernel,
                         cudaFuncAttributeMaxDynamicSharedMemorySize, dynsm);

    prep_W_kernel<<<104, 512>>>(W1, W2, Wq);
    fused_mlp_kernel<<<NBLK, NTHREADS, dynsm>>>(S, b1, b2, bq, Wh, bh, out);
}